// round 1
// baseline (speedup 1.0000x reference)
#include <cuda_runtime.h>

#define BATCH 8
#define HIMG 80
#define WIMG 80
#define CDIM 768
#define NPOS (HIMG * WIMG)        // 6400
#define CQKV (3 * CDIM)           // 2304
#define WIN 14
#define NWIN 6                    // 84/14
#define NHEAD 12
#define HD 64
#define NWP (WIN * WIN)           // 196

// Scratch (allocation-free rule: __device__ globals)
__device__ float g_qkv[(size_t)BATCH * NPOS * CQKV];   // ~472 MB
__device__ float g_att[(size_t)BATCH * NPOS * CDIM];   // ~157 MB

// ---------------------------------------------------------------------------
// Tiled SGEMM: C[M,N] = A[M,K] * B[K,N] (+bias). 128x128 tile, BK=8,
// 256 threads, 8x8 per thread. M%128==0, N%128==0, K%8==0 assumed.
// ---------------------------------------------------------------------------
__global__ __launch_bounds__(256) void sgemm_128x128(
    const float* __restrict__ A, const float* __restrict__ B,
    const float* __restrict__ bias, float* __restrict__ C,
    int M, int N, int K)
{
    __shared__ float As[8][128];
    __shared__ float Bs[8][128];

    const int tid = threadIdx.x;
    const int bm = blockIdx.y * 128;
    const int bn = blockIdx.x * 128;
    const int tx = tid & 15;        // 0..15 -> 8 cols each
    const int ty = tid >> 4;        // 0..15 -> 8 rows each

    // A-tile load mapping: 128 rows x 8 cols = 1024 floats; one float4/thread
    const int arow = tid >> 1;          // 0..127
    const int acol = (tid & 1) * 4;     // 0 or 4
    // B-tile load mapping: 8 rows x 128 cols; one float4/thread
    const int brow = tid >> 5;          // 0..7
    const int bcol = (tid & 31) * 4;    // 0..124

    const float* Aptr = A + (size_t)(bm + arow) * K + acol;
    const float* Bptr = B + (size_t)brow * N + bn + bcol;

    float acc[8][8];
#pragma unroll
    for (int i = 0; i < 8; i++)
#pragma unroll
        for (int j = 0; j < 8; j++) acc[i][j] = 0.f;

    for (int k0 = 0; k0 < K; k0 += 8) {
        float4 av = *(const float4*)(Aptr + k0);
        float4 bv = *(const float4*)(Bptr + (size_t)k0 * N);
        __syncthreads();   // protect previous-iteration smem reads
        As[acol + 0][arow] = av.x;
        As[acol + 1][arow] = av.y;
        As[acol + 2][arow] = av.z;
        As[acol + 3][arow] = av.w;
        *(float4*)&Bs[brow][bcol] = bv;
        __syncthreads();

#pragma unroll
        for (int kk = 0; kk < 8; kk++) {
            float a[8], b[8];
            *(float4*)(a)     = *(const float4*)&As[kk][ty * 8];
            *(float4*)(a + 4) = *(const float4*)&As[kk][ty * 8 + 4];
            *(float4*)(b)     = *(const float4*)&Bs[kk][tx * 8];
            *(float4*)(b + 4) = *(const float4*)&Bs[kk][tx * 8 + 4];
#pragma unroll
            for (int i = 0; i < 8; i++)
#pragma unroll
                for (int j = 0; j < 8; j++)
                    acc[i][j] = fmaf(a[i], b[j], acc[i][j]);
        }
    }

    const int row0 = bm + ty * 8;
    const int col0 = bn + tx * 8;
    float bvals[8];
#pragma unroll
    for (int j = 0; j < 8; j++) bvals[j] = bias ? bias[col0 + j] : 0.f;

#pragma unroll
    for (int i = 0; i < 8; i++) {
#pragma unroll
        for (int j = 0; j < 8; j += 4) {
            float4 v;
            v.x = acc[i][j + 0] + bvals[j + 0];
            v.y = acc[i][j + 1] + bvals[j + 1];
            v.z = acc[i][j + 2] + bvals[j + 2];
            v.w = acc[i][j + 3] + bvals[j + 3];
            *(float4*)(C + (size_t)(row0 + i) * N + col0 + j) = v;
        }
    }
}

// ---------------------------------------------------------------------------
// Windowed attention: one block per (b, window, head).
// K,V [196,64] staged in smem (zeros at padded positions — reference pads
// BEFORE softmax, so padded keys legitimately contribute exp(0-m)).
// Each of 196 threads owns one query row; online softmax over 196 keys.
// ---------------------------------------------------------------------------
__global__ __launch_bounds__(256) void win_attn(
    const float* __restrict__ qkv, float* __restrict__ out)
{
    const int idx  = blockIdx.x;
    const int head = idx % NHEAD;
    const int l    = (idx / NHEAD) % (NWIN * NWIN);
    const int b    = idx / (NHEAD * NWIN * NWIN);
    const int wi = l / NWIN, wj = l % NWIN;

    extern __shared__ float sm[];
    float* Ks = sm;                 // [196][64]
    float* Vs = sm + NWP * HD;      // [196][64]

    const int tid = threadIdx.x;

    // Stage K,V (float4 granularity): 196 * 16 float4 per matrix
    for (int i = tid; i < NWP * (HD / 4); i += blockDim.x) {
        const int p = i / (HD / 4);
        const int f = i % (HD / 4);
        const int r = p / WIN, c = p % WIN;
        const int h = wi * WIN + r, w = wj * WIN + c;
        float4 kv = make_float4(0.f, 0.f, 0.f, 0.f);
        float4 vv = make_float4(0.f, 0.f, 0.f, 0.f);
        if (h < HIMG && w < WIMG) {
            const size_t base =
                (size_t)(b * NPOS + h * WIMG + w) * CQKV + head * HD + f * 4;
            kv = *(const float4*)(qkv + base + CDIM);
            vv = *(const float4*)(qkv + base + 2 * CDIM);
        }
        ((float4*)Ks)[i] = kv;
        ((float4*)Vs)[i] = vv;
    }
    __syncthreads();

    if (tid < NWP) {
        const int r = tid / WIN, c = tid % WIN;
        const int h = wi * WIN + r, w = wj * WIN + c;
        if (h < HIMG && w < WIMG) {  // padded query rows are discarded by ref
            const size_t qbase =
                (size_t)(b * NPOS + h * WIMG + w) * CQKV + head * HD;
            float q[HD];
#pragma unroll
            for (int d = 0; d < HD; d += 4) {
                float4 t = *(const float4*)(qkv + qbase + d);
                q[d] = t.x; q[d + 1] = t.y; q[d + 2] = t.z; q[d + 3] = t.w;
            }

            float m = -1e30f, lsum = 0.f;
            float acc[HD];
#pragma unroll
            for (int d = 0; d < HD; d++) acc[d] = 0.f;

            for (int j = 0; j < NWP; j++) {
                const float* kj = Ks + j * HD;
                float s = 0.f;
#pragma unroll
                for (int d = 0; d < HD; d++) s = fmaf(q[d], kj[d], s);
                s *= 0.125f;  // hd^-0.5
                if (s > m) {
                    const float corr = __expf(m - s);
                    lsum *= corr;
#pragma unroll
                    for (int d = 0; d < HD; d++) acc[d] *= corr;
                    m = s;
                }
                const float pexp = __expf(s - m);
                lsum += pexp;
                const float* vj = Vs + j * HD;
#pragma unroll
                for (int d = 0; d < HD; d++)
                    acc[d] = fmaf(pexp, vj[d], acc[d]);
            }

            const float inv = 1.f / lsum;
            const size_t obase =
                (size_t)(b * NPOS + h * WIMG + w) * CDIM + head * HD;
#pragma unroll
            for (int d = 0; d < HD; d += 4) {
                float4 t;
                t.x = acc[d] * inv; t.y = acc[d + 1] * inv;
                t.z = acc[d + 2] * inv; t.w = acc[d + 3] * inv;
                *(float4*)(out + obase + d) = t;
            }
        }
    }
}

// ---------------------------------------------------------------------------
extern "C" void kernel_launch(void* const* d_in, const int* in_sizes, int n_in,
                              void* d_out, int out_size)
{
    const float* x     = (const float*)d_in[0];
    const float* Wqkv  = (const float*)d_in[1];
    const float* Wproj = (const float*)d_in[2];
    const float* bproj = (const float*)d_in[3];
    float* out = (float*)d_out;

    float* qkv; float* att;
    cudaGetSymbolAddress((void**)&qkv, g_qkv);
    cudaGetSymbolAddress((void**)&att, g_att);

    const int M = BATCH * NPOS;    // 51200

    // 1) qkv = x @ Wqkv   [51200,768]x[768,2304]
    {
        dim3 grid(CQKV / 128, M / 128);
        sgemm_128x128<<<grid, 256>>>(x, Wqkv, nullptr, qkv, M, CQKV, CDIM);
    }

    // 2) windowed attention
    {
        const int smem = 2 * NWP * HD * (int)sizeof(float);  // 100352 B
        cudaFuncSetAttribute(win_attn,
                             cudaFuncAttributeMaxDynamicSharedMemorySize, smem);
        dim3 grid(BATCH * NWIN * NWIN * NHEAD);              // 3456
        win_attn<<<grid, 256, smem>>>(qkv, att);
    }

    // 3) out = att @ Wproj + bproj   [51200,768]x[768,768]
    {
        dim3 grid(CDIM / 128, M / 128);
        sgemm_128x128<<<grid, 256>>>(att, Wproj, bproj, out, M, CDIM, CDIM);
    }
}

// round 5
// speedup vs baseline: 1.1285x; 1.1285x over previous
#include <cuda_runtime.h>
#include <cuda_bf16.h>
#include <cstdint>

#define BATCH 8
#define HIMG 80
#define WIMG 80
#define CDIM 768
#define NPOS (HIMG * WIMG)        // 6400
#define CQKV (3 * CDIM)           // 2304
#define WIN 14
#define NWIN 6
#define NHEAD 12
#define HD 64
#define NWP (WIN * WIN)           // 196
#define MROWS (BATCH * NPOS)      // 51200

// ---------------- scratch (__device__ globals: allocation-free rule) -------
__device__ float g_qkv[(size_t)MROWS * CQKV];            // fp32 qkv
__device__ float g_att[(size_t)MROWS * CDIM];            // fp32 attention out
__device__ __nv_bfloat16 g_ahi[(size_t)MROWS * CDIM];    // A hi (x or att)
__device__ __nv_bfloat16 g_alo[(size_t)MROWS * CDIM];    // A lo
__device__ __nv_bfloat16 g_bhi[(size_t)CQKV * CDIM];     // W^T hi (max size)
__device__ __nv_bfloat16 g_blo[(size_t)CQKV * CDIM];     // W^T lo

// ---------------- PTX helpers (NO 'a'-suffix features) ---------------------
__device__ __forceinline__ uint32_t smem_u32(const void* p) {
    uint32_t a;
    asm("{ .reg .u64 t; cvta.to.shared.u64 t, %1; cvt.u32.u64 %0, t; }"
        : "=r"(a) : "l"(p));
    return a;
}
__device__ __forceinline__ void cp_async16(uint32_t dst, const void* src) {
    asm volatile("cp.async.cg.shared.global [%0], [%1], 16;"
                 :: "r"(dst), "l"(src));
}
#define CP_COMMIT() asm volatile("cp.async.commit_group;" ::: "memory")
#define CP_WAIT(n)  asm volatile("cp.async.wait_group %0;" :: "n"(n) : "memory")

__device__ __forceinline__ void ldm_x4(uint32_t* r, uint32_t addr) {
    asm volatile("ldmatrix.sync.aligned.m8n8.x4.shared.b16 {%0,%1,%2,%3}, [%4];"
                 : "=r"(r[0]), "=r"(r[1]), "=r"(r[2]), "=r"(r[3]) : "r"(addr));
}
__device__ __forceinline__ void mma_bf16(float* d, const uint32_t* a,
                                         uint32_t b0, uint32_t b1) {
    asm volatile(
        "mma.sync.aligned.m16n8k16.row.col.f32.bf16.bf16.f32 "
        "{%0,%1,%2,%3}, {%4,%5,%6,%7}, {%8,%9}, {%0,%1,%2,%3};"
        : "+f"(d[0]), "+f"(d[1]), "+f"(d[2]), "+f"(d[3])
        : "r"(a[0]), "r"(a[1]), "r"(a[2]), "r"(a[3]), "r"(b0), "r"(b1));
}

// ---------------------------------------------------------------------------
// bf16x3 GEMM via mma.sync: C[M,N] = Ah*Bh + Ah*Bl + Al*Bh (+bias), fp32 acc.
// A[M,K] row-major bf16 hi/lo; B stored transposed [N,K] row-major bf16 hi/lo.
// 128x128 tile, BK=64, 256 threads (8 warps, each 64x32), cp.async double buf.
// smem tile: 128 rows x 64 bf16 = 128B/row, 16B-column XOR-by-row swizzle.
// ---------------------------------------------------------------------------
#define BM 128
#define BN 128
#define BK 64
#define TILE_B (BM * BK * 2)        // 16384
#define BUF_B  (4 * TILE_B)         // 65536 (Ah,Al,Bh,Bl)
#define GEMM_SMEM (2 * BUF_B)       // 131072

__global__ __launch_bounds__(256) void gemm_mma_bf16x3(
    const __nv_bfloat16* __restrict__ Ah, const __nv_bfloat16* __restrict__ Al,
    const __nv_bfloat16* __restrict__ Bh, const __nv_bfloat16* __restrict__ Bl,
    const float* __restrict__ bias, float* __restrict__ C,
    int M, int N, int K)
{
    extern __shared__ char sm[];
    const uint32_t smb = smem_u32(sm);
    const int tid  = threadIdx.x;
    const int wid  = tid >> 5;
    const int lane = tid & 31;
    const int bm = blockIdx.y * BM;
    const int bn = blockIdx.x * BN;
    const int warp_m = (wid >> 2) * 64;   // 0 or 64
    const int warp_n = (wid & 3) * 32;    // 0,32,64,96

    const __nv_bfloat16* gA[2] = { Ah + (size_t)bm * K, Al + (size_t)bm * K };
    const __nv_bfloat16* gB[2] = { Bh + (size_t)bn * K, Bl + (size_t)bn * K };

    float acc[4][4][4];
#pragma unroll
    for (int i = 0; i < 4; i++)
#pragma unroll
        for (int j = 0; j < 4; j++)
#pragma unroll
            for (int k = 0; k < 4; k++) acc[i][j][k] = 0.f;

    const int nchunk = K / BK;

    // ---- chunk loader: 4 tiles x 16KB, swizzled cp.async ----
    auto load_chunk = [&](int c) {
        const uint32_t bufb = smb + (c & 1) * BUF_B;
        const int k0 = c * BK;
#pragma unroll
        for (int t = 0; t < 4; t++) {
            const __nv_bfloat16* src = (t < 2 ? gA[t] : gB[t - 2]) + k0;
            const uint32_t dstb = bufb + t * TILE_B;
#pragma unroll
            for (int i = 0; i < 4; i++) {
                const int idx = i * 256 + tid;        // 0..1023
                const int row = idx >> 3, cc = idx & 7;
                const uint32_t sw = row * 128 + ((cc ^ (row & 7)) << 4);
                cp_async16(dstb + sw, src + (size_t)row * K + cc * 8);
            }
        }
        CP_COMMIT();
    };

    load_chunk(0);

    const int lrow  = lane & 15;
    const int lhalf = lane >> 4;

    for (int c = 0; c < nchunk; c++) {
        if (c + 1 < nchunk) { load_chunk(c + 1); CP_WAIT(1); }
        else                { CP_WAIT(0); }
        __syncthreads();

        const uint32_t aHb = smb + (c & 1) * BUF_B;
        const uint32_t aLb = aHb + TILE_B;
        const uint32_t bHb = aHb + 2 * TILE_B;
        const uint32_t bLb = aHb + 3 * TILE_B;

#pragma unroll
        for (int ks = 0; ks < 4; ks++) {
            const int ccol = ks * 2 + lhalf;          // 16B column index
            uint32_t ah[4][4], al[4][4], bh[2][4], bl[2][4];
#pragma unroll
            for (int mi = 0; mi < 4; mi++) {
                const int row = warp_m + mi * 16 + lrow;
                const uint32_t off = row * 128 + ((ccol ^ (row & 7)) << 4);
                ldm_x4(ah[mi], aHb + off);
                ldm_x4(al[mi], aLb + off);
            }
#pragma unroll
            for (int j = 0; j < 2; j++) {
                const int row = warp_n + j * 16 + lrow;
                const uint32_t off = row * 128 + ((ccol ^ (row & 7)) << 4);
                ldm_x4(bh[j], bHb + off);
                ldm_x4(bl[j], bLb + off);
            }
#pragma unroll
            for (int mi = 0; mi < 4; mi++)
#pragma unroll
                for (int nj = 0; nj < 4; nj++) {
                    const int p = nj >> 1, s = nj & 1;
                    mma_bf16(acc[mi][nj], ah[mi], bh[p][s], bh[p][s + 2]);
                    mma_bf16(acc[mi][nj], ah[mi], bl[p][s], bl[p][s + 2]);
                    mma_bf16(acc[mi][nj], al[mi], bh[p][s], bh[p][s + 2]);
                }
        }
        __syncthreads();
    }

    // ---- epilogue ----
    const int row_t = lane >> 2;
    const int col_t = (lane & 3) * 2;
#pragma unroll
    for (int mi = 0; mi < 4; mi++) {
#pragma unroll
        for (int r = 0; r < 2; r++) {
            const int row = bm + warp_m + mi * 16 + row_t + r * 8;
            float* crow = C + (size_t)row * N + bn;
#pragma unroll
            for (int nj = 0; nj < 4; nj++) {
                const int col = warp_n + nj * 8 + col_t;
                float2 v;
                v.x = acc[mi][nj][r * 2 + 0];
                v.y = acc[mi][nj][r * 2 + 1];
                if (bias) { v.x += bias[bn + col]; v.y += bias[bn + col + 1]; }
                *(float2*)(crow + col) = v;
            }
        }
    }
}

// ---------------------------------------------------------------------------
// fp32 -> bf16 hi/lo split, row-major
// ---------------------------------------------------------------------------
__global__ __launch_bounds__(256) void split_rm(
    const float* __restrict__ in, __nv_bfloat16* __restrict__ hi,
    __nv_bfloat16* __restrict__ lo, int n4)
{
    int i = blockIdx.x * blockDim.x + threadIdx.x;
    if (i < n4) {
        float4 v = ((const float4*)in)[i];
        float f[4] = { v.x, v.y, v.z, v.w };
        __nv_bfloat16 h[4], l[4];
#pragma unroll
        for (int j = 0; j < 4; j++) {
            h[j] = __float2bfloat16_rn(f[j]);
            l[j] = __float2bfloat16_rn(f[j] - __bfloat162float(h[j]));
        }
        ((ushort4*)hi)[i] = make_ushort4(
            __bfloat16_as_ushort(h[0]), __bfloat16_as_ushort(h[1]),
            __bfloat16_as_ushort(h[2]), __bfloat16_as_ushort(h[3]));
        ((ushort4*)lo)[i] = make_ushort4(
            __bfloat16_as_ushort(l[0]), __bfloat16_as_ushort(l[1]),
            __bfloat16_as_ushort(l[2]), __bfloat16_as_ushort(l[3]));
    }
}

// fp32 W[K,N] -> transposed bf16 hi/lo [N,K]
__global__ __launch_bounds__(256) void split_tr(
    const float* __restrict__ W, __nv_bfloat16* __restrict__ hi,
    __nv_bfloat16* __restrict__ lo, int K, int N)
{
    int idx = blockIdx.x * blockDim.x + threadIdx.x;
    if (idx < K * N) {
        int n = idx / K, k = idx % K;
        float v = W[(size_t)k * N + n];
        __nv_bfloat16 h = __float2bfloat16_rn(v);
        hi[idx] = h;
        lo[idx] = __float2bfloat16_rn(v - __bfloat162float(h));
    }
}

// ---------------------------------------------------------------------------
// Windowed attention (fp32 SIMT, as in R1)
// ---------------------------------------------------------------------------
__global__ __launch_bounds__(256) void win_attn(
    const float* __restrict__ qkv, float* __restrict__ out)
{
    const int idx  = blockIdx.x;
    const int head = idx % NHEAD;
    const int l    = (idx / NHEAD) % (NWIN * NWIN);
    const int b    = idx / (NHEAD * NWIN * NWIN);
    const int wi = l / NWIN, wj = l % NWIN;

    extern __shared__ float smf[];
    float* Ks = smf;
    float* Vs = smf + NWP * HD;

    const int tid = threadIdx.x;

    for (int i = tid; i < NWP * (HD / 4); i += blockDim.x) {
        const int p = i / (HD / 4);
        const int f = i % (HD / 4);
        const int r = p / WIN, c = p % WIN;
        const int h = wi * WIN + r, w = wj * WIN + c;
        float4 kv = make_float4(0.f, 0.f, 0.f, 0.f);
        float4 vv = make_float4(0.f, 0.f, 0.f, 0.f);
        if (h < HIMG && w < WIMG) {
            const size_t base =
                (size_t)(b * NPOS + h * WIMG + w) * CQKV + head * HD + f * 4;
            kv = *(const float4*)(qkv + base + CDIM);
            vv = *(const float4*)(qkv + base + 2 * CDIM);
        }
        ((float4*)Ks)[i] = kv;
        ((float4*)Vs)[i] = vv;
    }
    __syncthreads();

    if (tid < NWP) {
        const int r = tid / WIN, c = tid % WIN;
        const int h = wi * WIN + r, w = wj * WIN + c;
        if (h < HIMG && w < WIMG) {
            const size_t qbase =
                (size_t)(b * NPOS + h * WIMG + w) * CQKV + head * HD;
            float q[HD];
#pragma unroll
            for (int d = 0; d < HD; d += 4) {
                float4 t = *(const float4*)(qkv + qbase + d);
                q[d] = t.x; q[d + 1] = t.y; q[d + 2] = t.z; q[d + 3] = t.w;
            }
            float m = -1e30f, lsum = 0.f;
            float acc[HD];
#pragma unroll
            for (int d = 0; d < HD; d++) acc[d] = 0.f;

            for (int j = 0; j < NWP; j++) {
                const float* kj = Ks + j * HD;
                float s = 0.f;
#pragma unroll
                for (int d = 0; d < HD; d++) s = fmaf(q[d], kj[d], s);
                s *= 0.125f;
                if (s > m) {
                    const float corr = __expf(m - s);
                    lsum *= corr;
#pragma unroll
                    for (int d = 0; d < HD; d++) acc[d] *= corr;
                    m = s;
                }
                const float pexp = __expf(s - m);
                lsum += pexp;
                const float* vj = Vs + j * HD;
#pragma unroll
                for (int d = 0; d < HD; d++)
                    acc[d] = fmaf(pexp, vj[d], acc[d]);
            }
            const float inv = 1.f / lsum;
            const size_t obase =
                (size_t)(b * NPOS + h * WIMG + w) * CDIM + head * HD;
#pragma unroll
            for (int d = 0; d < HD; d += 4) {
                float4 t;
                t.x = acc[d] * inv; t.y = acc[d + 1] * inv;
                t.z = acc[d + 2] * inv; t.w = acc[d + 3] * inv;
                *(float4*)(out + obase + d) = t;
            }
        }
    }
}

// ---------------------------------------------------------------------------
extern "C" void kernel_launch(void* const* d_in, const int* in_sizes, int n_in,
                              void* d_out, int out_size)
{
    const float* x     = (const float*)d_in[0];
    const float* Wqkv  = (const float*)d_in[1];
    const float* Wproj = (const float*)d_in[2];
    const float* bproj = (const float*)d_in[3];
    float* out = (float*)d_out;

    float *qkv, *att;
    __nv_bfloat16 *ahi, *alo, *bhi, *blo;
    cudaGetSymbolAddress((void**)&qkv, g_qkv);
    cudaGetSymbolAddress((void**)&att, g_att);
    cudaGetSymbolAddress((void**)&ahi, g_ahi);
    cudaGetSymbolAddress((void**)&alo, g_alo);
    cudaGetSymbolAddress((void**)&bhi, g_bhi);
    cudaGetSymbolAddress((void**)&blo, g_blo);

    cudaFuncSetAttribute(gemm_mma_bf16x3,
                         cudaFuncAttributeMaxDynamicSharedMemorySize, GEMM_SMEM);
    const int attn_smem = 2 * NWP * HD * (int)sizeof(float);
    cudaFuncSetAttribute(win_attn,
                         cudaFuncAttributeMaxDynamicSharedMemorySize, attn_smem);

    const int M = MROWS;

    // ---- GEMM1: qkv = x @ Wqkv ----
    {
        int n4 = M * CDIM / 4;
        split_rm<<<(n4 + 255) / 256, 256>>>(x, ahi, alo, n4);
        int ne = CDIM * CQKV;
        split_tr<<<(ne + 255) / 256, 256>>>(Wqkv, bhi, blo, CDIM, CQKV);
        dim3 grid(CQKV / BN, M / BM);
        gemm_mma_bf16x3<<<grid, 256, GEMM_SMEM>>>(
            ahi, alo, bhi, blo, nullptr, qkv, M, CQKV, CDIM);
    }

    // ---- windowed attention ----
    {
        dim3 grid(BATCH * NWIN * NWIN * NHEAD);
        win_attn<<<grid, 256, attn_smem>>>(qkv, att);
    }

    // ---- GEMM3: out = att @ Wproj + bproj ----
    {
        int n4 = M * CDIM / 4;
        split_rm<<<(n4 + 255) / 256, 256>>>(att, ahi, alo, n4);
        int ne = CDIM * CDIM;
        split_tr<<<(ne + 255) / 256, 256>>>(Wproj, bhi, blo, CDIM, CDIM);
        dim3 grid(CDIM / BN, M / BM);
        gemm_mma_bf16x3<<<grid, 256, GEMM_SMEM>>>(
            ahi, alo, bhi, blo, bproj, out, M, CDIM, CDIM);
    }
}

// round 8
// speedup vs baseline: 1.5876x; 1.4068x over previous
#include <cuda_runtime.h>
#include <cuda_bf16.h>
#include <cstdint>

#define BATCH 8
#define HIMG 80
#define WIMG 80
#define CDIM 768
#define NPOS (HIMG * WIMG)        // 6400
#define CQKV (3 * CDIM)           // 2304
#define WIN 14
#define NWIN 6
#define NHEAD 12
#define HD 64
#define NWP (WIN * WIN)           // 196
#define MROWS (BATCH * NPOS)      // 51200

// ---------------- scratch (__device__ globals: allocation-free rule) -------
__device__ float g_qkv[(size_t)MROWS * CQKV];
__device__ float g_att[(size_t)MROWS * CDIM];
__device__ __nv_bfloat16 g_ahi[(size_t)MROWS * CDIM];
__device__ __nv_bfloat16 g_alo[(size_t)MROWS * CDIM];
__device__ __nv_bfloat16 g_bhi[(size_t)CQKV * CDIM];
__device__ __nv_bfloat16 g_blo[(size_t)CQKV * CDIM];

// ---------------- PTX helpers (no 'a'-suffix features) ---------------------
__device__ __forceinline__ uint32_t smem_u32(const void* p) {
    uint32_t a;
    asm("{ .reg .u64 t; cvta.to.shared.u64 t, %1; cvt.u32.u64 %0, t; }"
        : "=r"(a) : "l"(p));
    return a;
}
__device__ __forceinline__ void cp_async16(uint32_t dst, const void* src) {
    asm volatile("cp.async.cg.shared.global [%0], [%1], 16;"
                 :: "r"(dst), "l"(src));
}
#define CP_COMMIT() asm volatile("cp.async.commit_group;" ::: "memory")
#define CP_WAIT(n)  asm volatile("cp.async.wait_group %0;" :: "n"(n) : "memory")

__device__ __forceinline__ void ldm_x4(uint32_t* r, uint32_t addr) {
    asm volatile("ldmatrix.sync.aligned.m8n8.x4.shared.b16 {%0,%1,%2,%3}, [%4];"
                 : "=r"(r[0]), "=r"(r[1]), "=r"(r[2]), "=r"(r[3]) : "r"(addr));
}
__device__ __forceinline__ void mma_bf16(float* d, const uint32_t* a,
                                         uint32_t b0, uint32_t b1) {
    asm volatile(
        "mma.sync.aligned.m16n8k16.row.col.f32.bf16.bf16.f32 "
        "{%0,%1,%2,%3}, {%4,%5,%6,%7}, {%8,%9}, {%0,%1,%2,%3};"
        : "+f"(d[0]), "+f"(d[1]), "+f"(d[2]), "+f"(d[3])
        : "r"(a[0]), "r"(a[1]), "r"(a[2]), "r"(a[3]), "r"(b0), "r"(b1));
}

// ---------------------------------------------------------------------------
// bf16x3 GEMM via mma.sync: C = Ah*Bh + Ah*Bl + Al*Bh (+bias), fp32 acc.
// 128x128 tile, BK=32, 3-stage cp.async ring (96KB smem), 256 thr, 2 CTA/SM.
// smem rows are 64B (4 x 16B cols), swizzle: col ^ ((row>>1)&3).
// ---------------------------------------------------------------------------
#define BM 128
#define BN 128
#define BK 32
#define STAGES 3
#define TILE_B (BM * BK * 2)          // 8192
#define STAGE_B (4 * TILE_B)          // 32768 (Ah,Al,Bh,Bl)
#define GEMM_SMEM (STAGES * STAGE_B)  // 98304

__global__ __launch_bounds__(256, 2) void gemm_mma_bf16x3(
    const __nv_bfloat16* __restrict__ Ah, const __nv_bfloat16* __restrict__ Al,
    const __nv_bfloat16* __restrict__ Bh, const __nv_bfloat16* __restrict__ Bl,
    const float* __restrict__ bias, float* __restrict__ C,
    int M, int N, int K)
{
    extern __shared__ char sm[];
    const uint32_t smb = smem_u32(sm);
    const int tid  = threadIdx.x;
    const int wid  = tid >> 5;
    const int lane = tid & 31;
    const int bm = blockIdx.y * BM;
    const int bn = blockIdx.x * BN;
    const int warp_m = (wid >> 2) * 64;   // 0 or 64
    const int warp_n = (wid & 3) * 32;    // 0,32,64,96

    const __nv_bfloat16* gA[2] = { Ah + (size_t)bm * K, Al + (size_t)bm * K };
    const __nv_bfloat16* gB[2] = { Bh + (size_t)bn * K, Bl + (size_t)bn * K };

    float acc[4][4][4];
#pragma unroll
    for (int i = 0; i < 4; i++)
#pragma unroll
        for (int j = 0; j < 4; j++)
#pragma unroll
            for (int k = 0; k < 4; k++) acc[i][j][k] = 0.f;

    const int nchunk = K / BK;   // 24

    auto load_chunk = [&](int c) {
        const uint32_t bufb = smb + (c % STAGES) * STAGE_B;
        const int k0 = c * BK;
#pragma unroll
        for (int t = 0; t < 4; t++) {
            const __nv_bfloat16* src = (t < 2 ? gA[t] : gB[t - 2]) + k0;
            const uint32_t dstb = bufb + t * TILE_B;
#pragma unroll
            for (int i = 0; i < 2; i++) {
                const int idx = i * 256 + tid;          // 0..511
                const int row = idx >> 2, cc = idx & 3; // 4 x 16B per row
                const uint32_t sw = row * 64 + ((cc ^ ((row >> 1) & 3)) << 4);
                cp_async16(dstb + sw, src + (size_t)row * K + cc * 8);
            }
        }
        CP_COMMIT();
    };

    load_chunk(0);
    load_chunk(1);

    const int lrow  = lane & 15;
    const int lhalf = lane >> 4;

    for (int c = 0; c < nchunk; c++) {
        if (c + 1 < nchunk) CP_WAIT(1);
        else                CP_WAIT(0);
        __syncthreads();
        if (c + 2 < nchunk) load_chunk(c + 2);

        const uint32_t aHb = smb + (c % STAGES) * STAGE_B;
        const uint32_t aLb = aHb + TILE_B;
        const uint32_t bHb = aHb + 2 * TILE_B;
        const uint32_t bLb = aHb + 3 * TILE_B;

#pragma unroll
        for (int ks = 0; ks < 2; ks++) {
            const int ccol = ks * 2 + lhalf;            // 16B col 0..3
            uint32_t bh[2][4], bl[2][4];
#pragma unroll
            for (int j = 0; j < 2; j++) {
                const int row = warp_n + j * 16 + lrow;
                const uint32_t off = row * 64 + ((ccol ^ ((row >> 1) & 3)) << 4);
                ldm_x4(bh[j], bHb + off);
                ldm_x4(bl[j], bLb + off);
            }
#pragma unroll
            for (int mi = 0; mi < 4; mi++) {
                const int row = warp_m + mi * 16 + lrow;
                const uint32_t off = row * 64 + ((ccol ^ ((row >> 1) & 3)) << 4);
                uint32_t ah[4], al[4];
                ldm_x4(ah, aHb + off);
                ldm_x4(al, aLb + off);
#pragma unroll
                for (int nj = 0; nj < 4; nj++) {
                    const int p = nj >> 1, s = nj & 1;
                    mma_bf16(acc[mi][nj], ah, bh[p][s], bh[p][s + 2]);
                    mma_bf16(acc[mi][nj], ah, bl[p][s], bl[p][s + 2]);
                    mma_bf16(acc[mi][nj], al, bh[p][s], bh[p][s + 2]);
                }
            }
        }
        __syncthreads();
    }

    // ---- epilogue ----
    const int row_t = lane >> 2;
    const int col_t = (lane & 3) * 2;
#pragma unroll
    for (int mi = 0; mi < 4; mi++) {
#pragma unroll
        for (int r = 0; r < 2; r++) {
            const int row = bm + warp_m + mi * 16 + row_t + r * 8;
            float* crow = C + (size_t)row * N + bn;
#pragma unroll
            for (int nj = 0; nj < 4; nj++) {
                const int col = warp_n + nj * 8 + col_t;
                float2 v;
                v.x = acc[mi][nj][r * 2 + 0];
                v.y = acc[mi][nj][r * 2 + 1];
                if (bias) { v.x += bias[bn + col]; v.y += bias[bn + col + 1]; }
                *(float2*)(crow + col) = v;
            }
        }
    }
}

// ---------------------------------------------------------------------------
// fp32 -> bf16 hi/lo splits
// ---------------------------------------------------------------------------
__global__ __launch_bounds__(256) void split_rm(
    const float* __restrict__ in, __nv_bfloat16* __restrict__ hi,
    __nv_bfloat16* __restrict__ lo, int n4)
{
    int i = blockIdx.x * blockDim.x + threadIdx.x;
    if (i < n4) {
        float4 v = ((const float4*)in)[i];
        float f[4] = { v.x, v.y, v.z, v.w };
        __nv_bfloat16 h[4], l[4];
#pragma unroll
        for (int j = 0; j < 4; j++) {
            h[j] = __float2bfloat16_rn(f[j]);
            l[j] = __float2bfloat16_rn(f[j] - __bfloat162float(h[j]));
        }
        ((ushort4*)hi)[i] = make_ushort4(
            __bfloat16_as_ushort(h[0]), __bfloat16_as_ushort(h[1]),
            __bfloat16_as_ushort(h[2]), __bfloat16_as_ushort(h[3]));
        ((ushort4*)lo)[i] = make_ushort4(
            __bfloat16_as_ushort(l[0]), __bfloat16_as_ushort(l[1]),
            __bfloat16_as_ushort(l[2]), __bfloat16_as_ushort(l[3]));
    }
}

__global__ __launch_bounds__(256) void split_tr(
    const float* __restrict__ W, __nv_bfloat16* __restrict__ hi,
    __nv_bfloat16* __restrict__ lo, int K, int N)
{
    int idx = blockIdx.x * blockDim.x + threadIdx.x;
    if (idx < K * N) {
        int n = idx / K, k = idx % K;
        float v = W[(size_t)k * N + n];
        __nv_bfloat16 h = __float2bfloat16_rn(v);
        hi[idx] = h;
        lo[idx] = __float2bfloat16_rn(v - __bfloat162float(h));
    }
}

// ---------------------------------------------------------------------------
// Windowed attention: thread-PAIR per query row (each owns 32 of 64 dims).
// Block 416 threads handles one (b, window, head). K,V staged fp32 in smem.
// ---------------------------------------------------------------------------
#define ATTN_THREADS 416

__global__ __launch_bounds__(ATTN_THREADS) void win_attn(
    const float* __restrict__ qkv, float* __restrict__ out)
{
    const int idx  = blockIdx.x;
    const int head = idx % NHEAD;
    const int l    = (idx / NHEAD) % (NWIN * NWIN);
    const int b    = idx / (NHEAD * NWIN * NWIN);
    const int wi = l / NWIN, wj = l % NWIN;

    extern __shared__ float smf[];
    float* Ks = smf;               // [196][64]
    float* Vs = smf + NWP * HD;    // [196][64]

    const int tid = threadIdx.x;

    for (int i = tid; i < NWP * (HD / 4); i += ATTN_THREADS) {
        const int p = i / (HD / 4);
        const int f = i % (HD / 4);
        const int r = p / WIN, c = p % WIN;
        const int h = wi * WIN + r, w = wj * WIN + c;
        float4 kv = make_float4(0.f, 0.f, 0.f, 0.f);
        float4 vv = make_float4(0.f, 0.f, 0.f, 0.f);
        if (h < HIMG && w < WIMG) {
            const size_t base =
                (size_t)(b * NPOS + h * WIMG + w) * CQKV + head * HD + f * 4;
            kv = *(const float4*)(qkv + base + CDIM);
            vv = *(const float4*)(qkv + base + 2 * CDIM);
        }
        ((float4*)Ks)[i] = kv;
        ((float4*)Vs)[i] = vv;
    }
    __syncthreads();

    // pair decomposition: row = tid>>1, half = tid&1 owns dims [half*32, +32)
    const int row  = tid >> 1;          // 0..207
    const int half = tid & 1;
    const int r = row / WIN, c = row % WIN;
    const int h = wi * WIN + r, w = wj * WIN + c;
    const bool valid = (row < NWP) && (h < HIMG) && (w < WIMG);
    const int hc = h < HIMG ? h : HIMG - 1;
    const int wc = w < WIMG ? w : WIMG - 1;

    const size_t qbase =
        (size_t)(b * NPOS + hc * WIMG + wc) * CQKV + head * HD + half * 32;
    float4 q4[8];
#pragma unroll
    for (int d = 0; d < 8; d++)
        q4[d] = *(const float4*)(qkv + qbase + d * 4);

    float m = -1e30f, lsum = 0.f;
    float acc[32];
#pragma unroll
    for (int d = 0; d < 32; d++) acc[d] = 0.f;

    for (int j = 0; j < NWP; j++) {
        const float4* kj = (const float4*)(Ks + j * HD + half * 32);
        float s0 = 0.f, s1 = 0.f, s2 = 0.f, s3 = 0.f;
#pragma unroll
        for (int d = 0; d < 8; d++) {
            float4 kv = kj[d];
            s0 = fmaf(q4[d].x, kv.x, s0);
            s1 = fmaf(q4[d].y, kv.y, s1);
            s2 = fmaf(q4[d].z, kv.z, s2);
            s3 = fmaf(q4[d].w, kv.w, s3);
        }
        float sh = (s0 + s1) + (s2 + s3);
        float s = sh + __shfl_xor_sync(0xffffffffu, sh, 1);
        s *= 0.125f;
        if (s > m) {
            const float corr = __expf(m - s);
            lsum *= corr;
#pragma unroll
            for (int d = 0; d < 32; d++) acc[d] *= corr;
            m = s;
        }
        const float p = __expf(s - m);
        lsum += p;
        const float* vj = Vs + j * HD + half * 32;
#pragma unroll
        for (int d = 0; d < 32; d++)
            acc[d] = fmaf(p, vj[d], acc[d]);
    }

    if (valid) {
        const float inv = 1.f / lsum;
        const size_t obase =
            (size_t)(b * NPOS + h * WIMG + w) * CDIM + head * HD + half * 32;
#pragma unroll
        for (int d = 0; d < 32; d += 4) {
            float4 t;
            t.x = acc[d] * inv; t.y = acc[d + 1] * inv;
            t.z = acc[d + 2] * inv; t.w = acc[d + 3] * inv;
            *(float4*)(out + obase + d) = t;
        }
    }
}

// ---------------------------------------------------------------------------
extern "C" void kernel_launch(void* const* d_in, const int* in_sizes, int n_in,
                              void* d_out, int out_size)
{
    const float* x     = (const float*)d_in[0];
    const float* Wqkv  = (const float*)d_in[1];
    const float* Wproj = (const float*)d_in[2];
    const float* bproj = (const float*)d_in[3];
    float* out = (float*)d_out;

    float *qkv, *att;
    __nv_bfloat16 *ahi, *alo, *bhi, *blo;
    cudaGetSymbolAddress((void**)&qkv, g_qkv);
    cudaGetSymbolAddress((void**)&att, g_att);
    cudaGetSymbolAddress((void**)&ahi, g_ahi);
    cudaGetSymbolAddress((void**)&alo, g_alo);
    cudaGetSymbolAddress((void**)&bhi, g_bhi);
    cudaGetSymbolAddress((void**)&blo, g_blo);

    cudaFuncSetAttribute(gemm_mma_bf16x3,
                         cudaFuncAttributeMaxDynamicSharedMemorySize, GEMM_SMEM);
    const int attn_smem = 2 * NWP * HD * (int)sizeof(float);
    cudaFuncSetAttribute(win_attn,
                         cudaFuncAttributeMaxDynamicSharedMemorySize, attn_smem);

    const int M = MROWS;

    // ---- GEMM1: qkv = x @ Wqkv ----
    {
        int n4 = M * CDIM / 4;
        split_rm<<<(n4 + 255) / 256, 256>>>(x, ahi, alo, n4);
        int ne = CDIM * CQKV;
        split_tr<<<(ne + 255) / 256, 256>>>(Wqkv, bhi, blo, CDIM, CQKV);
        dim3 grid(CQKV / BN, M / BM);
        gemm_mma_bf16x3<<<grid, 256, GEMM_SMEM>>>(
            ahi, alo, bhi, blo, nullptr, qkv, M, CQKV, CDIM);
    }

    // ---- windowed attention ----
    {
        dim3 grid(BATCH * NWIN * NWIN * NHEAD);
        win_attn<<<grid, ATTN_THREADS, attn_smem>>>(qkv, att);
    }

    // ---- GEMM3: out = att @ Wproj + bproj ----
    {
        int n4 = M * CDIM / 4;
        split_rm<<<(n4 + 255) / 256, 256>>>(att, ahi, alo, n4);
        int ne = CDIM * CDIM;
        split_tr<<<(ne + 255) / 256, 256>>>(Wproj, bhi, blo, CDIM, CDIM);
        dim3 grid(CDIM / BN, M / BM);
        gemm_mma_bf16x3<<<grid, 256, GEMM_SMEM>>>(
            ahi, alo, bhi, blo, bproj, out, M, CDIM, CDIM);
    }
}